// round 5
// baseline (speedup 1.0000x reference)
#include <cuda_runtime.h>
#include <cuda_bf16.h>

// GraphSAGE 6-layer: dims 128->32->32->32->32->32->16
//  - p = h@Wl computed BEFORE aggregation (linearity of mean)
//  - CSR built once per launch; per-layer aggregation = pure gather (no float atomics)
//  - out = h@Wr + bl from GEMM kernel; aggregate adds mean(p[neighbors])
//  - ReLU folded into next layer's GEMM input read
//  - edge_index dtype (int64 vs int32) detected on-device (in-bounds for both)

#define NN 100000
#define EE 3200000

__device__ int   g_is32;
__device__ int   g_srcc[EE];
__device__ int   g_dstc[EE];
__device__ int   g_csrc[EE];
__device__ int   g_deg[NN];
__device__ int   g_cur[NN];
__device__ int   g_off[NN + 1];
__device__ float g_inv[NN];
__device__ float g_p [NN * 32];
__device__ float g_h0[NN * 32];
__device__ float g_h1[NN * 32];

// ---------------------------------------------------------------------------
// Detect whether the edge buffer is int64 or int32.
// Sample ONLY indices < e: as int64 reads these touch bytes [0, 8e), which is
// in-bounds whether the buffer is int64 (16e bytes) or int32 (8e bytes).
// If int64: every sampled value is a valid node id in [0, n).
// If int32: each 8-byte read packs two int32 indices; the hi word is a random
// src index, nonzero w.p. ~1-1e-5 per sample -> 128 samples make detection sure.
__global__ void detect_kernel(const long long* __restrict__ ei, int e, int n) {
    if (threadIdx.x == 0 && blockIdx.x == 0) {
        int bad = 0;
        for (int i = 0; i < 128; i++) {
            long long v = ei[i];
            if (v < 0 || v >= (long long)n) bad++;
        }
        g_is32 = (bad > 0) ? 1 : 0;
    }
}

__global__ void zero_deg_kernel(int n) {
    int i = blockIdx.x * blockDim.x + threadIdx.x;
    if (i < n) g_deg[i] = 0;
}

// split edge_index into int32 src/dst, count in-degree
__global__ void prep_kernel(const void* __restrict__ eiv, int e, int n) {
    int i = blockIdx.x * blockDim.x + threadIdx.x;
    if (i >= e) return;
    int s, d;
    if (g_is32) {
        const int* p = (const int*)eiv;
        s = p[i];
        d = p[e + i];
    } else {
        const long long* p = (const long long*)eiv;
        s = (int)p[i];
        d = (int)p[(size_t)e + i];
    }
    if ((unsigned)s >= (unsigned)n || (unsigned)d >= (unsigned)n) {
        g_srcc[i] = -1;
        g_dstc[i] = -1;
        return;
    }
    g_srcc[i] = s;
    g_dstc[i] = d;
    atomicAdd(&g_deg[d], 1);
}

// single-block exclusive scan of g_deg -> g_off / g_cur, plus inv degree
__global__ void scan_offsets_kernel(int n) {
    __shared__ int s_carry;
    __shared__ int s_wsum[32];
    if (threadIdx.x == 0) s_carry = 0;
    __syncthreads();
    int lane = threadIdx.x & 31;
    int w    = threadIdx.x >> 5;
    for (int base = 0; base < n; base += 1024) {
        int i = base + (int)threadIdx.x;
        int v = (i < n) ? g_deg[i] : 0;
        int x = v;
        #pragma unroll
        for (int o = 1; o < 32; o <<= 1) {
            int t = __shfl_up_sync(0xffffffffu, x, o);
            if (lane >= o) x += t;
        }
        if (lane == 31) s_wsum[w] = x;
        __syncthreads();
        if (w == 0) {
            int ws = s_wsum[lane];
            #pragma unroll
            for (int o = 1; o < 32; o <<= 1) {
                int t = __shfl_up_sync(0xffffffffu, ws, o);
                if (lane >= o) ws += t;
            }
            s_wsum[lane] = ws;
        }
        __syncthreads();
        int prefix = s_carry + ((w == 0) ? 0 : s_wsum[w - 1]);
        int incl   = prefix + x;
        if (i < n) {
            int excl = incl - v;
            g_off[i] = excl;
            g_cur[i] = excl;
            g_inv[i] = 1.0f / (float)(v > 0 ? v : 1);
        }
        __syncthreads();
        if (threadIdx.x == 1023) s_carry = incl;
        __syncthreads();
    }
    if (threadIdx.x == 0) g_off[n] = s_carry;
}

// bucket src indices by dst
__global__ void fill_kernel(int e) {
    int i = blockIdx.x * blockDim.x + threadIdx.x;
    if (i < e) {
        int d = g_dstc[i];
        if (d < 0) return;
        int slot = atomicAdd(&g_cur[d], 1);
        if (slot >= 0 && slot < EE) g_csrc[slot] = g_srcc[i];
    }
}

// ---------------------------------------------------------------------------
// Fused dual GEMM: p = relu?(h) @ Wl ; out = relu?(h) @ Wr + bl
template <int DIN, int DOUT, bool RELU_IN>
__global__ __launch_bounds__(256) void gemm_fused(
    const float* __restrict__ h,
    const float* __restrict__ Wl, const float* __restrict__ Wr,
    const float* __restrict__ bl,
    float* __restrict__ p, float* __restrict__ out, int n)
{
    constexpr int NPW = 32 / DOUT;   // nodes per warp
    __shared__ float sWl[DIN * DOUT];
    __shared__ float sWr[DIN * DOUT];
    __shared__ float sb[DOUT];
    for (int i = threadIdx.x; i < DIN * DOUT; i += blockDim.x) {
        sWl[i] = Wl[i];
        sWr[i] = Wr[i];
    }
    if (threadIdx.x < DOUT) sb[threadIdx.x] = bl[threadIdx.x];
    __syncthreads();

    int lane  = threadIdx.x & 31;
    int gwarp = (blockIdx.x * blockDim.x + threadIdx.x) >> 5;
    int sub   = lane / DOUT;
    int l     = lane % DOUT;
    int node  = gwarp * NPW + sub;
    if (node >= n) return;

    const float4* hrow = reinterpret_cast<const float4*>(h) + (size_t)node * (DIN / 4);
    float al = 0.f, ar = 0.f;
    #pragma unroll
    for (int k4 = 0; k4 < DIN / 4; k4++) {
        float4 hv = __ldg(&hrow[k4]);
        if (RELU_IN) {
            hv.x = fmaxf(hv.x, 0.f); hv.y = fmaxf(hv.y, 0.f);
            hv.z = fmaxf(hv.z, 0.f); hv.w = fmaxf(hv.w, 0.f);
        }
        int k = 4 * k4;
        al = fmaf(hv.x, sWl[(k + 0) * DOUT + l], al);
        ar = fmaf(hv.x, sWr[(k + 0) * DOUT + l], ar);
        al = fmaf(hv.y, sWl[(k + 1) * DOUT + l], al);
        ar = fmaf(hv.y, sWr[(k + 1) * DOUT + l], ar);
        al = fmaf(hv.z, sWl[(k + 2) * DOUT + l], al);
        ar = fmaf(hv.z, sWr[(k + 2) * DOUT + l], ar);
        al = fmaf(hv.w, sWl[(k + 3) * DOUT + l], al);
        ar = fmaf(hv.w, sWr[(k + 3) * DOUT + l], ar);
    }
    p  [(size_t)node * DOUT + l] = al;
    out[(size_t)node * DOUT + l] = ar + sb[l];
}

// ---------------------------------------------------------------------------
// out[node] += inv_deg[node] * sum_{j in N(node)} p[j]   (pure gather)
template <int DOUT>
__global__ __launch_bounds__(256) void aggregate_kernel(
    const float* __restrict__ p, float* __restrict__ out, int n)
{
    constexpr int NPW = 32 / DOUT;
    int lane  = threadIdx.x & 31;
    int gwarp = (blockIdx.x * blockDim.x + threadIdx.x) >> 5;
    int sub   = lane / DOUT;
    int l     = lane % DOUT;
    int node  = gwarp * NPW + sub;
    if (node >= n) return;

    int beg = g_off[node];
    int end = g_off[node + 1];
    float acc0 = 0.f, acc1 = 0.f;
    int i = beg;
    for (; i + 8 <= end; i += 8) {
        int s0 = __ldg(&g_csrc[i + 0]);
        int s1 = __ldg(&g_csrc[i + 1]);
        int s2 = __ldg(&g_csrc[i + 2]);
        int s3 = __ldg(&g_csrc[i + 3]);
        int s4 = __ldg(&g_csrc[i + 4]);
        int s5 = __ldg(&g_csrc[i + 5]);
        int s6 = __ldg(&g_csrc[i + 6]);
        int s7 = __ldg(&g_csrc[i + 7]);
        float v0 = __ldg(&p[(size_t)s0 * DOUT + l]);
        float v1 = __ldg(&p[(size_t)s1 * DOUT + l]);
        float v2 = __ldg(&p[(size_t)s2 * DOUT + l]);
        float v3 = __ldg(&p[(size_t)s3 * DOUT + l]);
        float v4 = __ldg(&p[(size_t)s4 * DOUT + l]);
        float v5 = __ldg(&p[(size_t)s5 * DOUT + l]);
        float v6 = __ldg(&p[(size_t)s6 * DOUT + l]);
        float v7 = __ldg(&p[(size_t)s7 * DOUT + l]);
        acc0 += v0; acc1 += v1; acc0 += v2; acc1 += v3;
        acc0 += v4; acc1 += v5; acc0 += v6; acc1 += v7;
    }
    for (; i < end; i++)
        acc0 += __ldg(&p[(size_t)g_csrc[i] * DOUT + l]);

    out[(size_t)node * DOUT + l] += (acc0 + acc1) * g_inv[node];
}

// ---------------------------------------------------------------------------
extern "C" void kernel_launch(void* const* d_in, const int* in_sizes, int n_in,
                              void* d_out, int out_size)
{
    const float* x  = (const float*)d_in[0];
    const void*  ei = d_in[1];
    const float *Wl[6], *bl[6], *Wr[6];
    for (int i = 0; i < 6; i++) {
        Wl[i] = (const float*)d_in[2 + 3 * i];
        bl[i] = (const float*)d_in[3 + 3 * i];
        Wr[i] = (const float*)d_in[4 + 3 * i];
    }
    float* out = (float*)d_out;
    const int n = NN, e = EE;

    float *pp = nullptr, *ph0 = nullptr, *ph1 = nullptr;
    cudaGetSymbolAddress((void**)&pp,  g_p);
    cudaGetSymbolAddress((void**)&ph0, g_h0);
    cudaGetSymbolAddress((void**)&ph1, g_h1);

    // ---- CSR build (once per launch) ----
    detect_kernel<<<1, 32>>>((const long long*)ei, e, n);
    zero_deg_kernel<<<(n + 255) / 256, 256>>>(n);
    prep_kernel<<<(e + 255) / 256, 256>>>(ei, e, n);
    scan_offsets_kernel<<<1, 1024>>>(n);
    fill_kernel<<<(e + 255) / 256, 256>>>(e);

    const int blocks32 = (n * 32 + 255) / 256;             // NPW=1 (DOUT=32)
    const int blocks16 = (((n + 1) / 2) * 32 + 255) / 256; // NPW=2 (DOUT=16)

    // layer 0: x(128) -> h0(32)
    gemm_fused<128, 32, false><<<blocks32, 256>>>(x, Wl[0], Wr[0], bl[0], pp, ph0, n);
    aggregate_kernel<32><<<blocks32, 256>>>(pp, ph0, n);
    // layer 1: h0 -> h1 (relu on read)
    gemm_fused<32, 32, true><<<blocks32, 256>>>(ph0, Wl[1], Wr[1], bl[1], pp, ph1, n);
    aggregate_kernel<32><<<blocks32, 256>>>(pp, ph1, n);
    // layer 2: h1 -> h0
    gemm_fused<32, 32, true><<<blocks32, 256>>>(ph1, Wl[2], Wr[2], bl[2], pp, ph0, n);
    aggregate_kernel<32><<<blocks32, 256>>>(pp, ph0, n);
    // layer 3: h0 -> h1
    gemm_fused<32, 32, true><<<blocks32, 256>>>(ph0, Wl[3], Wr[3], bl[3], pp, ph1, n);
    aggregate_kernel<32><<<blocks32, 256>>>(pp, ph1, n);
    // layer 4: h1 -> h0
    gemm_fused<32, 32, true><<<blocks32, 256>>>(ph1, Wl[4], Wr[4], bl[4], pp, ph0, n);
    aggregate_kernel<32><<<blocks32, 256>>>(pp, ph0, n);
    // layer 5: h0 -> d_out (16), no relu after
    gemm_fused<32, 16, true><<<blocks16, 256>>>(ph0, Wl[5], Wr[5], bl[5], pp, out, n);
    aggregate_kernel<16><<<blocks16, 256>>>(pp, out, n);
}

// round 6
// speedup vs baseline: 1.1037x; 1.1037x over previous
#include <cuda_runtime.h>
#include <cuda_bf16.h>

// GraphSAGE 6-layer: dims 128->32->32->32->32->32->16
//  - p = h@Wl computed BEFORE aggregation (linearity of mean)
//  - CSR built once per launch; per-layer aggregation = pure gather (no float atomics)
//  - out = h@Wr + bl from GEMM kernel; aggregate adds mean(p[neighbors])
//  - ReLU folded into next layer's GEMM input read
//  - edge_index dtype (int64 vs int32) detected on-device (in-bounds for both)
//  - R6: hierarchical parallel scan (was 107us single-block), parallel detect

#define NN 100000
#define EE 3200000
#define SCAN_NB ((NN + 1023) / 1024)   // 98 blocks

__device__ int   g_is32;
__device__ int   g_srcc[EE];
__device__ int   g_dstc[EE];
__device__ int   g_csrc[EE];
__device__ int   g_deg[NN];
__device__ int   g_cur[NN];
__device__ int   g_off[NN + 1];
__device__ int   g_bsum[128];
__device__ int   g_boff[128];
__device__ float g_inv[NN];
__device__ float g_p [NN * 32];
__device__ float g_h0[NN * 32];
__device__ float g_h1[NN * 32];

// ---------------------------------------------------------------------------
// Detect int64 vs int32 edge buffer. Reads only indices < e (in-bounds for both
// layouts). int64 -> all values valid node ids; int32 -> 8-byte read packs two
// indices, hi word nonzero w.p. ~1-1e-5 per sample.
__global__ void detect_kernel(const long long* __restrict__ ei, int n) {
    __shared__ int s_bad;
    if (threadIdx.x == 0) s_bad = 0;
    __syncthreads();
    long long v = ei[threadIdx.x];           // 128 threads, indices 0..127
    if (v < 0 || v >= (long long)n) atomicAdd(&s_bad, 1);
    __syncthreads();
    if (threadIdx.x == 0) g_is32 = (s_bad > 0) ? 1 : 0;
}

__global__ void zero_deg_kernel(int n) {
    int i = blockIdx.x * blockDim.x + threadIdx.x;
    if (i < n) g_deg[i] = 0;
}

// split edge_index into int32 src/dst, count in-degree
__global__ void prep_kernel(const void* __restrict__ eiv, int e, int n) {
    int i = blockIdx.x * blockDim.x + threadIdx.x;
    if (i >= e) return;
    int s, d;
    if (g_is32) {
        const int* p = (const int*)eiv;
        s = p[i];
        d = p[e + i];
    } else {
        const long long* p = (const long long*)eiv;
        s = (int)p[i];
        d = (int)p[(size_t)e + i];
    }
    if ((unsigned)s >= (unsigned)n || (unsigned)d >= (unsigned)n) {
        g_srcc[i] = -1;
        g_dstc[i] = -1;
        return;
    }
    g_srcc[i] = s;
    g_dstc[i] = d;
    atomicAdd(&g_deg[d], 1);
}

// ---------------------------------------------------------------------------
// Hierarchical scan, stage A: block-local exclusive scan of g_deg (1024/block),
// block-local exclusive value -> g_off[i], block total -> g_bsum[blockIdx].
__global__ __launch_bounds__(1024) void scan_blocks_kernel(int n) {
    __shared__ int s_wsum[32];
    int i    = blockIdx.x * 1024 + threadIdx.x;
    int lane = threadIdx.x & 31;
    int w    = threadIdx.x >> 5;
    int v = (i < n) ? g_deg[i] : 0;
    int x = v;
    #pragma unroll
    for (int o = 1; o < 32; o <<= 1) {
        int t = __shfl_up_sync(0xffffffffu, x, o);
        if (lane >= o) x += t;
    }
    if (lane == 31) s_wsum[w] = x;
    __syncthreads();
    if (w == 0) {
        int ws = s_wsum[lane];
        #pragma unroll
        for (int o = 1; o < 32; o <<= 1) {
            int t = __shfl_up_sync(0xffffffffu, ws, o);
            if (lane >= o) ws += t;
        }
        s_wsum[lane] = ws;
    }
    __syncthreads();
    int incl = x + ((w == 0) ? 0 : s_wsum[w - 1]);
    if (i < n) g_off[i] = incl - v;          // block-local exclusive
    if (threadIdx.x == 1023) g_bsum[blockIdx.x] = incl;  // block total
}

// Stage B: 1 block (128 threads) scans the block totals; grand total -> g_off[n].
__global__ void scan_bsums_kernel(int nb, int n) {
    __shared__ int s_wsum[4];
    int lane = threadIdx.x & 31;
    int w    = threadIdx.x >> 5;
    int v = (threadIdx.x < nb) ? g_bsum[threadIdx.x] : 0;
    int x = v;
    #pragma unroll
    for (int o = 1; o < 32; o <<= 1) {
        int t = __shfl_up_sync(0xffffffffu, x, o);
        if (lane >= o) x += t;
    }
    if (lane == 31) s_wsum[w] = x;
    __syncthreads();
    if (w == 0 && lane < 4) {
        int ws = s_wsum[lane];
        #pragma unroll
        for (int o = 1; o < 4; o <<= 1) {
            int t = __shfl_up_sync(0x0000000fu, ws, o);
            if (lane >= o) ws += t;
        }
        s_wsum[lane] = ws;
    }
    __syncthreads();
    int incl = x + ((w == 0) ? 0 : s_wsum[w - 1]);
    g_boff[threadIdx.x] = incl - v;          // exclusive block offset
    if (threadIdx.x == 127) g_off[n] = incl; // grand total (= E valid edges)
}

// Stage C: add block offsets, emit g_cur and inverse degree.
__global__ __launch_bounds__(1024) void finalize_offsets_kernel(int n) {
    int i = blockIdx.x * 1024 + threadIdx.x;
    if (i < n) {
        int off = g_off[i] + g_boff[blockIdx.x];
        g_off[i] = off;
        g_cur[i] = off;
        int v = g_deg[i];
        g_inv[i] = 1.0f / (float)(v > 0 ? v : 1);
    }
}

// bucket src indices by dst
__global__ void fill_kernel(int e) {
    int i = blockIdx.x * blockDim.x + threadIdx.x;
    if (i < e) {
        int d = g_dstc[i];
        if (d < 0) return;
        int slot = atomicAdd(&g_cur[d], 1);
        if (slot >= 0 && slot < EE) g_csrc[slot] = g_srcc[i];
    }
}

// ---------------------------------------------------------------------------
// Fused dual GEMM: p = relu?(h) @ Wl ; out = relu?(h) @ Wr + bl
template <int DIN, int DOUT, bool RELU_IN>
__global__ __launch_bounds__(256) void gemm_fused(
    const float* __restrict__ h,
    const float* __restrict__ Wl, const float* __restrict__ Wr,
    const float* __restrict__ bl,
    float* __restrict__ p, float* __restrict__ out, int n)
{
    constexpr int NPW = 32 / DOUT;   // nodes per warp
    __shared__ float sWl[DIN * DOUT];
    __shared__ float sWr[DIN * DOUT];
    __shared__ float sb[DOUT];
    for (int i = threadIdx.x; i < DIN * DOUT; i += blockDim.x) {
        sWl[i] = Wl[i];
        sWr[i] = Wr[i];
    }
    if (threadIdx.x < DOUT) sb[threadIdx.x] = bl[threadIdx.x];
    __syncthreads();

    int lane  = threadIdx.x & 31;
    int gwarp = (blockIdx.x * blockDim.x + threadIdx.x) >> 5;
    int sub   = lane / DOUT;
    int l     = lane % DOUT;
    int node  = gwarp * NPW + sub;
    if (node >= n) return;

    const float4* hrow = reinterpret_cast<const float4*>(h) + (size_t)node * (DIN / 4);
    float al = 0.f, ar = 0.f;
    #pragma unroll
    for (int k4 = 0; k4 < DIN / 4; k4++) {
        float4 hv = __ldg(&hrow[k4]);
        if (RELU_IN) {
            hv.x = fmaxf(hv.x, 0.f); hv.y = fmaxf(hv.y, 0.f);
            hv.z = fmaxf(hv.z, 0.f); hv.w = fmaxf(hv.w, 0.f);
        }
        int k = 4 * k4;
        al = fmaf(hv.x, sWl[(k + 0) * DOUT + l], al);
        ar = fmaf(hv.x, sWr[(k + 0) * DOUT + l], ar);
        al = fmaf(hv.y, sWl[(k + 1) * DOUT + l], al);
        ar = fmaf(hv.y, sWr[(k + 1) * DOUT + l], ar);
        al = fmaf(hv.z, sWl[(k + 2) * DOUT + l], al);
        ar = fmaf(hv.z, sWr[(k + 2) * DOUT + l], ar);
        al = fmaf(hv.w, sWl[(k + 3) * DOUT + l], al);
        ar = fmaf(hv.w, sWr[(k + 3) * DOUT + l], ar);
    }
    p  [(size_t)node * DOUT + l] = al;
    out[(size_t)node * DOUT + l] = ar + sb[l];
}

// ---------------------------------------------------------------------------
// out[node] += inv_deg[node] * sum_{j in N(node)} p[j]   (pure gather)
template <int DOUT>
__global__ __launch_bounds__(256) void aggregate_kernel(
    const float* __restrict__ p, float* __restrict__ out, int n)
{
    constexpr int NPW = 32 / DOUT;
    int lane  = threadIdx.x & 31;
    int gwarp = (blockIdx.x * blockDim.x + threadIdx.x) >> 5;
    int sub   = lane / DOUT;
    int l     = lane % DOUT;
    int node  = gwarp * NPW + sub;
    if (node >= n) return;

    int beg = g_off[node];
    int end = g_off[node + 1];
    float acc0 = 0.f, acc1 = 0.f;
    int i = beg;
    for (; i + 8 <= end; i += 8) {
        int s0 = __ldg(&g_csrc[i + 0]);
        int s1 = __ldg(&g_csrc[i + 1]);
        int s2 = __ldg(&g_csrc[i + 2]);
        int s3 = __ldg(&g_csrc[i + 3]);
        int s4 = __ldg(&g_csrc[i + 4]);
        int s5 = __ldg(&g_csrc[i + 5]);
        int s6 = __ldg(&g_csrc[i + 6]);
        int s7 = __ldg(&g_csrc[i + 7]);
        float v0 = __ldg(&p[(size_t)s0 * DOUT + l]);
        float v1 = __ldg(&p[(size_t)s1 * DOUT + l]);
        float v2 = __ldg(&p[(size_t)s2 * DOUT + l]);
        float v3 = __ldg(&p[(size_t)s3 * DOUT + l]);
        float v4 = __ldg(&p[(size_t)s4 * DOUT + l]);
        float v5 = __ldg(&p[(size_t)s5 * DOUT + l]);
        float v6 = __ldg(&p[(size_t)s6 * DOUT + l]);
        float v7 = __ldg(&p[(size_t)s7 * DOUT + l]);
        acc0 += v0; acc1 += v1; acc0 += v2; acc1 += v3;
        acc0 += v4; acc1 += v5; acc0 += v6; acc1 += v7;
    }
    for (; i + 4 <= end; i += 4) {
        int s0 = __ldg(&g_csrc[i + 0]);
        int s1 = __ldg(&g_csrc[i + 1]);
        int s2 = __ldg(&g_csrc[i + 2]);
        int s3 = __ldg(&g_csrc[i + 3]);
        acc0 += __ldg(&p[(size_t)s0 * DOUT + l]);
        acc1 += __ldg(&p[(size_t)s1 * DOUT + l]);
        acc0 += __ldg(&p[(size_t)s2 * DOUT + l]);
        acc1 += __ldg(&p[(size_t)s3 * DOUT + l]);
    }
    for (; i < end; i++)
        acc0 += __ldg(&p[(size_t)g_csrc[i] * DOUT + l]);

    out[(size_t)node * DOUT + l] += (acc0 + acc1) * g_inv[node];
}

// ---------------------------------------------------------------------------
extern "C" void kernel_launch(void* const* d_in, const int* in_sizes, int n_in,
                              void* d_out, int out_size)
{
    const float* x  = (const float*)d_in[0];
    const void*  ei = d_in[1];
    const float *Wl[6], *bl[6], *Wr[6];
    for (int i = 0; i < 6; i++) {
        Wl[i] = (const float*)d_in[2 + 3 * i];
        bl[i] = (const float*)d_in[3 + 3 * i];
        Wr[i] = (const float*)d_in[4 + 3 * i];
    }
    float* out = (float*)d_out;
    const int n = NN, e = EE;

    float *pp = nullptr, *ph0 = nullptr, *ph1 = nullptr;
    cudaGetSymbolAddress((void**)&pp,  g_p);
    cudaGetSymbolAddress((void**)&ph0, g_h0);
    cudaGetSymbolAddress((void**)&ph1, g_h1);

    // ---- CSR build (once per launch) ----
    detect_kernel<<<1, 128>>>((const long long*)ei, n);
    zero_deg_kernel<<<(n + 255) / 256, 256>>>(n);
    prep_kernel<<<(e + 255) / 256, 256>>>(ei, e, n);
    scan_blocks_kernel<<<SCAN_NB, 1024>>>(n);
    scan_bsums_kernel<<<1, 128>>>(SCAN_NB, n);
    finalize_offsets_kernel<<<SCAN_NB, 1024>>>(n);
    fill_kernel<<<(e + 255) / 256, 256>>>(e);

    const int blocks32 = (n * 32 + 255) / 256;             // NPW=1 (DOUT=32)
    const int blocks16 = (((n + 1) / 2) * 32 + 255) / 256; // NPW=2 (DOUT=16)

    // layer 0: x(128) -> h0(32)
    gemm_fused<128, 32, false><<<blocks32, 256>>>(x, Wl[0], Wr[0], bl[0], pp, ph0, n);
    aggregate_kernel<32><<<blocks32, 256>>>(pp, ph0, n);
    // layer 1: h0 -> h1 (relu on read)
    gemm_fused<32, 32, true><<<blocks32, 256>>>(ph0, Wl[1], Wr[1], bl[1], pp, ph1, n);
    aggregate_kernel<32><<<blocks32, 256>>>(pp, ph1, n);
    // layer 2: h1 -> h0
    gemm_fused<32, 32, true><<<blocks32, 256>>>(ph1, Wl[2], Wr[2], bl[2], pp, ph0, n);
    aggregate_kernel<32><<<blocks32, 256>>>(pp, ph0, n);
    // layer 3: h0 -> h1
    gemm_fused<32, 32, true><<<blocks32, 256>>>(ph0, Wl[3], Wr[3], bl[3], pp, ph1, n);
    aggregate_kernel<32><<<blocks32, 256>>>(pp, ph1, n);
    // layer 4: h1 -> h0
    gemm_fused<32, 32, true><<<blocks32, 256>>>(ph1, Wl[4], Wr[4], bl[4], pp, ph0, n);
    aggregate_kernel<32><<<blocks32, 256>>>(pp, ph0, n);
    // layer 5: h0 -> d_out (16), no relu after
    gemm_fused<32, 16, true><<<blocks16, 256>>>(ph0, Wl[5], Wr[5], bl[5], pp, out, n);
    aggregate_kernel<16><<<blocks16, 256>>>(pp, out, n);
}